// round 4
// baseline (speedup 1.0000x reference)
#include <cuda_runtime.h>
#include <math.h>

#define SS   2048
#define BB   64
#define IIN  256
#define HHID 512
#define EEMB 256
#define BH   (BB * HHID)              // 32768
#define OUT_HT ((size_t)SS * BH)      // 67108864
#define OUT_MT (OUT_HT + BH)
#define GRID_C 128

// ---------------- device scratch ----------------
__device__ float g_Wc[HHID * HHID];   // Wc = Wm @ We   [H][H]
__device__ float g_bvec[HHID];        // b_ih + Wm @ b_embed
__device__ unsigned g_count = 0;
__device__ volatile unsigned g_gen = 0;

// ---------------- kernel A: prep Wc, bvec ----------------
__global__ __launch_bounds__(256) void prep_kernel(
    const float* __restrict__ W_ih, const float* __restrict__ W_embed,
    const float* __restrict__ b_ih, const float* __restrict__ b_embed)
{
    __shared__ float wm[EEMB];
    int h1 = blockIdx.x;              // 0..511
    int tid = threadIdx.x;            // 0..255
    wm[tid] = W_ih[(size_t)h1 * (IIN + EEMB) + IIN + tid];
    __syncthreads();

    float a0 = 0.f, a1 = 0.f;
    #pragma unroll 4
    for (int e = 0; e < EEMB; e++) {
        float w = wm[e];
        a0 = fmaf(w, W_embed[(size_t)e * HHID + tid],       a0);
        a1 = fmaf(w, W_embed[(size_t)e * HHID + tid + 256], a1);
    }
    g_Wc[(size_t)h1 * HHID + tid]       = a0;
    g_Wc[(size_t)h1 * HHID + tid + 256] = a1;

    if (tid == 0) {
        float s = b_ih[h1];
        for (int e = 0; e < EEMB; e++) s = fmaf(wm[e], b_embed[e], s);
        g_bvec[h1] = s;
    }
}

// ---------------- kernel B: P = X @ Wx^T (in-place into out) ----------------
// M = S*B = 131072, N = H = 512, K = I = 256. Tile 64x64, 256 thr, 4x4/thread.
__global__ __launch_bounds__(256) void gemm_p_kernel(
    const float* __restrict__ x, const float* __restrict__ W_ih,
    float* __restrict__ out)
{
    __shared__ float As[32][68];      // [k][m]
    __shared__ float Bs[32][68];      // [k][n]
    int tid = threadIdx.x;
    int n0 = blockIdx.x * 64;         // 8 blocks
    int m0 = blockIdx.y * 64;         // 2048 blocks
    int tx = tid & 15, ty = tid >> 4;

    float acc[4][4];
    #pragma unroll
    for (int i = 0; i < 4; i++)
        #pragma unroll
        for (int j = 0; j < 4; j++) acc[i][j] = 0.f;

    for (int k0 = 0; k0 < IIN; k0 += 32) {
        #pragma unroll
        for (int i = 0; i < 2; i++) {
            int f = tid + i * 256;    // 0..511
            int row = f >> 3;         // 0..63
            int kq  = (f & 7) << 2;   // 0..28
            float4 v = *reinterpret_cast<const float4*>(
                x + (size_t)(m0 + row) * IIN + k0 + kq);
            As[kq+0][row] = v.x; As[kq+1][row] = v.y;
            As[kq+2][row] = v.z; As[kq+3][row] = v.w;
            float4 w = *reinterpret_cast<const float4*>(
                W_ih + (size_t)(n0 + row) * (IIN + EEMB) + k0 + kq);
            Bs[kq+0][row] = w.x; Bs[kq+1][row] = w.y;
            Bs[kq+2][row] = w.z; Bs[kq+3][row] = w.w;
        }
        __syncthreads();
        #pragma unroll
        for (int k = 0; k < 32; k++) {
            float4 a = *reinterpret_cast<const float4*>(&As[k][ty * 4]);
            float4 b = *reinterpret_cast<const float4*>(&Bs[k][tx * 4]);
            float av[4] = {a.x, a.y, a.z, a.w};
            float bv[4] = {b.x, b.y, b.z, b.w};
            #pragma unroll
            for (int i = 0; i < 4; i++)
                #pragma unroll
                for (int j = 0; j < 4; j++)
                    acc[i][j] = fmaf(av[i], bv[j], acc[i][j]);
        }
        __syncthreads();
    }

    #pragma unroll
    for (int i = 0; i < 4; i++) {
        float4 v = make_float4(acc[i][0], acc[i][1], acc[i][2], acc[i][3]);
        *reinterpret_cast<float4*>(
            out + (size_t)(m0 + ty * 4 + i) * HHID + n0 + tx * 4) = v;
    }
}

// ---------------- kernel C: persistent recurrence ----------------
// 128 CTAs: bid&1 = chain (even/odd t), bid>>1 = 8-col block of H.
// Per iter: t = 2*it + chain; h[t] = tanh(P[t] + h[t-2] @ Wc^T + b')
// (t==0 uses m_0 @ Wm^T + b_ih; t==1 uses h_0 as h[-1].)

__device__ __forceinline__ void gemm_acc(
    const float* __restrict__ Ap, int stride, int K,
    const float* __restrict__ Bsq, float (*As)[68],
    int tid, int rp, int c, float& acc0, float& acc1)
{
    for (int k0 = 0; k0 < K; k0 += 64) {
        #pragma unroll
        for (int i = 0; i < 4; i++) {
            int f = tid + i * 256;    // 0..1023
            int row = f >> 4;         // 0..63
            int kq  = (f & 15) << 2;  // 0..60
            float4 v = __ldcg(reinterpret_cast<const float4*>(
                Ap + (size_t)row * stride + k0 + kq));
            *reinterpret_cast<float4*>(&As[row][kq]) = v;
        }
        __syncthreads();
        #pragma unroll
        for (int k4 = 0; k4 < 16; k4++) {
            float4 a0 = *reinterpret_cast<const float4*>(&As[rp][k4 * 4]);
            float4 a1 = *reinterpret_cast<const float4*>(&As[rp + 32][k4 * 4]);
            const float* bp = Bsq + (((k0 + k4 * 4) << 3) + c);
            float b0 = bp[0], b1 = bp[8], b2 = bp[16], b3 = bp[24];
            acc0 = fmaf(a0.x, b0, acc0); acc0 = fmaf(a0.y, b1, acc0);
            acc0 = fmaf(a0.z, b2, acc0); acc0 = fmaf(a0.w, b3, acc0);
            acc1 = fmaf(a1.x, b0, acc1); acc1 = fmaf(a1.y, b1, acc1);
            acc1 = fmaf(a1.z, b2, acc1); acc1 = fmaf(a1.w, b3, acc1);
        }
        __syncthreads();
    }
}

__global__ __launch_bounds__(256) void rnn_rec_kernel(
    const float* __restrict__ h0, const float* __restrict__ m0,
    const float* __restrict__ W_embed, const float* __restrict__ b_embed,
    const float* __restrict__ b_ih, const float* __restrict__ W_ih,
    float* __restrict__ out)
{
    __shared__ float Bsc[HHID * 8];   // Wc slice  [k][c]
    __shared__ float Bsm[EEMB * 8];   // Wm slice  [k][c]  (t==0 only)
    __shared__ float As[64][68];
    __shared__ float hs[HHID];        // epilogue

    int tid = threadIdx.x;
    int bid = blockIdx.x;
    int chain = bid & 1;
    int col0 = (bid >> 1) * 8;
    int c  = tid & 7;
    int rp = tid >> 3;                // 0..31
    int col = col0 + c;

    // resident weight slices (SMEM for all 1024 iterations)
    #pragma unroll
    for (int i = 0; i < 16; i++) {
        int j = tid + i * 256;        // 0..4095
        int cc = j >> 9, k = j & 511;
        Bsc[k * 8 + cc] = g_Wc[(size_t)(col0 + cc) * HHID + k];
    }
    #pragma unroll
    for (int i = 0; i < 8; i++) {
        int j = tid + i * 256;        // 0..2047
        int cc = j >> 8, k = j & 255;
        Bsm[k * 8 + cc] = W_ih[(size_t)(col0 + cc) * (IIN + EEMB) + IIN + k];
    }

    unsigned base = 0;
    if (tid == 0) base = g_gen;       // stable at launch (no barrier in flight)
    __syncthreads();

    float bias_v = g_bvec[col];
    float bih_v  = b_ih[col];

    for (int it = 0; it < 1024; it++) {
        int t = 2 * it + chain;
        const float* P = out + (size_t)t * BH;
        float acc0 = P[(size_t)rp * HHID + col];
        float acc1 = P[(size_t)(rp + 32) * HHID + col];

        if (t == 0) {
            acc0 += bih_v; acc1 += bih_v;
            gemm_acc(m0, EEMB, EEMB, Bsm, As, tid, rp, c, acc0, acc1);
        } else {
            acc0 += bias_v; acc1 += bias_v;
            const float* Ap = (t == 1) ? h0 : (out + (size_t)(t - 2) * BH);
            gemm_acc(Ap, HHID, HHID, Bsc, As, tid, rp, c, acc0, acc1);
        }

        out[(size_t)t * BH + (size_t)rp * HHID + col]        = tanhf(acc0);
        out[(size_t)t * BH + (size_t)(rp + 32) * HHID + col] = tanhf(acc1);

        // ---- grid barrier (generation counting, wrap-safe) ----
        __threadfence();
        __syncthreads();
        if (tid == 0) {
            unsigned want = (unsigned)it + 1u;
            if (atomicAdd(&g_count, 1u) == GRID_C - 1u) {
                atomicExch(&g_count, 0u);
                __threadfence();
                g_gen = base + want;
            } else {
                while ((unsigned)(g_gen - base) < want) { __nanosleep(32); }
                __threadfence();
            }
        }
        __syncthreads();
    }

    // ---- epilogue: m_T and h_T ----
    if (bid < 64) {
        // m_T row b = bid : m_T[b][e] = b_embed[e] + sum_h h[2046][b][h]*We[e][h]
        const float* hrow = out + (size_t)2046 * BH + (size_t)bid * HHID;
        hs[tid]       = __ldcg(hrow + tid);
        hs[tid + 256] = __ldcg(hrow + tid + 256);
        __syncthreads();
        float acc = b_embed[tid];                 // e = tid
        const float* we = W_embed + (size_t)tid * HHID;
        #pragma unroll 4
        for (int h = 0; h < HHID; h++) acc = fmaf(hs[h], we[h], acc);
        out[OUT_MT + (size_t)bid * EEMB + tid] = acc;
    } else {
        // h_T = outputs[2047] : 64 CTAs x 512 floats
        int j = (bid - 64) * 512 + tid;
        out[OUT_HT + j]       = __ldcg(out + (size_t)2047 * BH + j);
        out[OUT_HT + j + 256] = __ldcg(out + (size_t)2047 * BH + j + 256);
    }
}

// ---------------- launch ----------------
extern "C" void kernel_launch(void* const* d_in, const int* in_sizes, int n_in,
                              void* d_out, int out_size) {
    const float* input_seq = (const float*)d_in[0];
    const float* h_0       = (const float*)d_in[1];
    const float* m_0       = (const float*)d_in[2];
    const float* W_embed   = (const float*)d_in[3];
    const float* b_embed   = (const float*)d_in[4];
    const float* W_ih      = (const float*)d_in[5];
    const float* b_ih      = (const float*)d_in[6];
    float* out = (float*)d_out;

    prep_kernel<<<HHID, 256>>>(W_ih, W_embed, b_ih, b_embed);
    gemm_p_kernel<<<dim3(8, 2048), 256>>>(input_seq, W_ih, out);
    rnn_rec_kernel<<<GRID_C, 256>>>(h_0, m_0, W_embed, b_embed, b_ih, W_ih, out);
}